// round 15
// baseline (speedup 1.0000x reference)
#include <cuda_runtime.h>
#include <cuda_fp16.h>
#include <math.h>
#include <stdint.h>

#define Bb 4
#define Ss 1024
#define Hh 1024
#define NHh 16
#define Dd 64
#define Pp 1024

#define INV_SCALE 0.07216878364870322f
#define QSCALE (0.07216878364870322f * 1.4426950408889634f)

/* ------------------------- scratch (fp16 operands) ------------------------- */
__device__ __half g_Q[(size_t)Bb * NHh * Ss * Dd];
__device__ __half g_K[(size_t)Bb * NHh * Ss * Dd];
__device__ __half g_VT[(size_t)Bb * NHh * Dd * Ss];
__device__ __half g_PK[(size_t)NHh * Pp * Dd];
__device__ __half g_PQ[(size_t)NHh * Pp * Dd];
__device__ __half g_CTX[(size_t)Bb * Ss * Hh];
__device__ float  g_Y[(size_t)Bb * Ss * Hh];
__device__ __half g_HS[(size_t)Bb * Ss * Hh];
__device__ __half g_RE[(size_t)Pp * Hh];
__device__ __half g_WINT[(size_t)3 * Hh * Hh];
__device__ __half g_WPKT[(size_t)Hh * Hh];
__device__ __half g_WPQT[(size_t)Hh * Hh];
__device__ __half g_WOT[(size_t)Hh * Hh];

/* ------------------------- helpers ------------------------- */
__device__ __forceinline__ void cp16(uint32_t dst, const void* src) {
    asm volatile("cp.async.cg.shared.global [%0], [%1], 16;" :: "r"(dst), "l"(src));
}
__device__ __forceinline__ void cp_commit() { asm volatile("cp.async.commit_group;"); }
template <int N> __device__ __forceinline__ void cp_wait() {
    asm volatile("cp.async.wait_group %0;" :: "n"(N));
}
__device__ __forceinline__ void ldsm4(uint32_t a[4], uint32_t addr) {
    asm volatile("ldmatrix.sync.aligned.m8n8.x4.shared.b16 {%0,%1,%2,%3}, [%4];"
                 : "=r"(a[0]), "=r"(a[1]), "=r"(a[2]), "=r"(a[3]) : "r"(addr));
}
__device__ __forceinline__ void ldsm2(uint32_t b[2], uint32_t addr) {
    asm volatile("ldmatrix.sync.aligned.m8n8.x2.shared.b16 {%0,%1}, [%2];"
                 : "=r"(b[0]), "=r"(b[1]) : "r"(addr));
}
__device__ __forceinline__ void mma16(float c[4], const uint32_t a[4], const uint32_t b[2]) {
    asm volatile(
        "mma.sync.aligned.m16n8k16.row.col.f32.f16.f16.f32 "
        "{%0,%1,%2,%3}, {%4,%5,%6,%7}, {%8,%9}, {%0,%1,%2,%3};"
        : "+f"(c[0]), "+f"(c[1]), "+f"(c[2]), "+f"(c[3])
        : "r"(a[0]), "r"(a[1]), "r"(a[2]), "r"(a[3]), "r"(b[0]), "r"(b[1]));
}
__device__ __forceinline__ uint32_t ex2h2(float e0, float e1) {
    __half2 h = __floats2half2_rn(e0, e1);
    uint32_t u = *(uint32_t*)&h, o;
    asm("ex2.approx.f16x2 %0, %1;" : "=r"(o) : "r"(u));
    return o;
}

#define SW_OFF(row, c) ((((row) << 3) + ((c) ^ ((row) & 7))) << 4)

/* ------------------------- prep kernels ------------------------- */
__global__ void __launch_bounds__(256) k_round2(const float* __restrict__ hs,
                                                const float* __restrict__ re) {
    int bx = blockIdx.x;
    const float* src;
    __half* dst;
    size_t i;
    if (bx < 4096) { src = hs; dst = g_HS; i = ((size_t)bx * 256 + threadIdx.x) * 4; }
    else { src = re; dst = g_RE; i = ((size_t)(bx - 4096) * 256 + threadIdx.x) * 4; }
    float4 v = *(const float4*)(src + i);
    *(__half2*)(dst + i) = __floats2half2_rn(v.x, v.y);
    *(__half2*)(dst + i + 2) = __floats2half2_rn(v.z, v.w);
}

__global__ void __launch_bounds__(256) k_transp2(const float* __restrict__ w_in,
                                                 const float* __restrict__ w_pk,
                                                 const float* __restrict__ w_pq,
                                                 const float* __restrict__ w_o, int z0) {
    int z = z0 + blockIdx.z;
    const float* src;
    __half* dst;
    int N, nbase;
    if (z < 3) { src = w_in; dst = g_WINT; N = 3072; nbase = z * 1024; }
    else if (z == 3) { src = w_pk; dst = g_WPKT; N = 1024; nbase = 0; }
    else if (z == 4) { src = w_pq; dst = g_WPQT; N = 1024; nbase = 0; }
    else { src = w_o; dst = g_WOT; N = 1024; nbase = 0; }
    __shared__ float s[32][33];
    int n0 = nbase + (blockIdx.x << 5), k0 = blockIdx.y << 5;
    int tx = threadIdx.x & 31, ty = threadIdx.x >> 5;
#pragma unroll
    for (int j = 0; j < 4; j++)
        s[ty + j * 8][tx] = src[(size_t)(k0 + ty + j * 8) * N + n0 + tx];
    __syncthreads();
#pragma unroll
    for (int j = 0; j < 4; j++)
        dst[(size_t)(n0 + ty + j * 8) * 1024 + k0 + tx] = __float2half_rn(s[tx][ty + j * 8]);
}

/* ------------------------- fp16 GEMM, 128x128 block, 3-stage pipeline, 2 CTAs/SM ------------------------- */
#define STAGE_B 32768u
#define GEMM_SMEM 98304

__global__ void __launch_bounds__(256, 2) gemm_all(int which,
                                                   const float* __restrict__ qb,
                                                   const float* __restrict__ vb,
                                                   const float* __restrict__ bpq,
                                                   const float* __restrict__ bo,
                                                   const float* __restrict__ hs) {
    constexpr int NS = 16;
    int bx = blockIdx.x;
    int mode, z = 0, m0, n0;
    const __half *A, *B;
    if (which == 4) {
        mode = 4; A = g_CTX; B = g_WOT;
        n0 = (bx & 7) << 7; m0 = (bx >> 3) << 7;
    } else if (bx < 768) {
        mode = 0; A = g_HS; B = g_WINT;
        n0 = (bx % 24) << 7; m0 = (bx / 24) << 7;
    } else {
        mode = 1; int i = bx - 768; z = i >> 6; int j = i & 63;
        A = g_RE; B = z ? g_WPQT : g_WPKT;
        n0 = (j & 7) << 7; m0 = (j >> 3) << 7;
    }

    extern __shared__ char smemc[];
    uint32_t sbase = (uint32_t)__cvta_generic_to_shared(smemc);

    int tid = threadIdx.x;
    int lane = tid & 31, wid = tid >> 5;
    int wm = wid & 1, wn = wid >> 1;

    int kcopy = tid & 7, rsub = tid >> 3;
    const __half* asrc0 = A + (size_t)(m0 + rsub) * 1024 + kcopy * 8;
    const __half* bsrc0 = B + (size_t)(n0 + rsub) * 1024 + kcopy * 8;

    float c[4][4][4];
#pragma unroll
    for (int i = 0; i < 4; i++)
#pragma unroll
        for (int j = 0; j < 4; j++)
#pragma unroll
            for (int r = 0; r < 4; r++) c[i][j][r] = 0.f;

#define STAGE_COPY(slot, kofs)                                                       \
    {                                                                                \
        uint32_t sb = sbase + (slot) * STAGE_B;                                      \
        _Pragma("unroll") for (int it = 0; it < 4; it++) {                           \
            int row = it * 32 + rsub;                                                \
            cp16(sb + SW_OFF(row, kcopy), asrc0 + (size_t)it * 32 * 1024 + (kofs));  \
        }                                                                            \
        _Pragma("unroll") for (int it = 0; it < 4; it++) {                           \
            int row = it * 32 + rsub;                                                \
            cp16(sb + 16384u + SW_OFF(row, kcopy),                                   \
                 bsrc0 + (size_t)it * 32 * 1024 + (kofs));                           \
        }                                                                            \
        cp_commit();                                                                 \
    }

    STAGE_COPY(0, 0)
    STAGE_COPY(1, 64)

    int arow_l = wm * 64 + (lane & 15);
    int akhalf = lane >> 4;
    int brow_base = wn * 32 + (lane & 7);
    int bkhalf = (lane >> 3) & 1;

    int slot = 0;
    for (int s = 0; s < NS; s++) {
        if (s + 2 < NS) {
            int nslot = slot + 2; if (nslot >= 3) nslot -= 3;
            STAGE_COPY(nslot, (s + 2) * 64)
            cp_wait<2>();
        } else if (s + 1 < NS) {
            cp_wait<1>();
        } else {
            cp_wait<0>();
        }
        __syncthreads();

        uint32_t sA = sbase + slot * STAGE_B;
        uint32_t sB = sA + 16384u;

#pragma unroll
        for (int kc = 0; kc < 4; kc++) {
            uint32_t bf[4][2];
#pragma unroll
            for (int nst = 0; nst < 4; nst++)
                ldsm2(bf[nst], sB + SW_OFF(brow_base + nst * 8, kc * 2 + bkhalf));
#pragma unroll
            for (int st = 0; st < 4; st++) {
                uint32_t af[4];
                ldsm4(af, sA + SW_OFF(arow_l + st * 16, kc * 2 + akhalf));
#pragma unroll
                for (int nst = 0; nst < 4; nst++) mma16(c[st][nst], af, bf[nst]);
            }
        }
        __syncthreads();
        if (++slot == 3) slot = 0;
    }

    int g = lane >> 2, q2 = lane & 3;
    int mbt = m0 + wm * 64, nbt = n0 + wn * 32;
#pragma unroll
    for (int st = 0; st < 4; st++) {
#pragma unroll
        for (int nst = 0; nst < 4; nst++) {
#pragma unroll
            for (int half = 0; half < 2; half++) {
                int m = mbt + st * 16 + g + half * 8;
                int n = nbt + nst * 8 + q2 * 2;
                float v0 = c[st][nst][half * 2 + 0];
                float v1 = c[st][nst][half * 2 + 1];
                if (mode == 0) {
                    int h = n / 192, rem = n - h * 192;
                    int t = rem >> 6, d = rem & 63;
                    int bq = m >> 10, srow = m & 1023;
                    size_t idx = (((size_t)(bq * 16 + h)) * 1024 + srow) * 64 + d;
                    if (t == 0) {
                        *(__half2*)&g_Q[idx] = __floats2half2_rn(
                            (v0 + qb[h * 64 + d]) * QSCALE,
                            (v1 + qb[h * 64 + d + 1]) * QSCALE);
                    } else if (t == 1) {
                        *(__half2*)&g_K[idx] = __floats2half2_rn(v0, v1);
                    } else {
                        size_t vt = (((size_t)(bq * 16 + h)) * 64 + d) * 1024 + srow;
                        g_VT[vt] = __float2half_rn(v0 + vb[h * 64 + d]);
                        g_VT[vt + 1024] = __float2half_rn(v1 + vb[h * 64 + d + 1]);
                    }
                } else if (mode == 1) {
                    int h = n >> 6, d = n & 63;
                    size_t idx = ((size_t)h * 1024 + m) * 64 + d;
                    if (z == 0) {
                        *(__half2*)&g_PK[idx] = __floats2half2_rn(v0, v1);
                    } else {
                        *(__half2*)&g_PQ[idx] = __floats2half2_rn(
                            (v0 + bpq[n]) * QSCALE, (v1 + bpq[n + 1]) * QSCALE);
                    }
                } else {
                    size_t o = (size_t)m * 1024 + n;
                    g_Y[o] = v0 + bo[n] + hs[o];
                    g_Y[o + 1] = v1 + bo[n + 1] + hs[o + 1];
                }
            }
        }
    }
#undef STAGE_COPY
}

/* ---------------- fused attention (best-known config, unchanged) ----
 * SMEM: Q@0(8K) K0@8K K1@16K V0@24K V1@32K B1@40K(16K) B2@56K(16K)
 *       C2k@72K(64*136*2) P2t@91136(64*72*2). total 100352. 2 CTAs/SM.
 */
#define CW 72
#define CRW 136
#define OFF_K0 8192u
#define OFF_K1 16384u
#define OFF_V0 24576u
#define OFF_V1 32768u
#define OFF_B1 40960u
#define OFF_B2 57344u
#define OFF_C2 73728u
#define OFF_P2 91136u
#define ATTN_SMEM 100352

__global__ void __launch_bounds__(128, 2) k_attn2() {
    extern __shared__ char smc[];
    uint32_t sb = (uint32_t)__cvta_generic_to_shared(smc);
    const uint32_t uQ = sb;
    const uint32_t uB1 = sb + OFF_B1;
    const uint32_t uB2 = sb + OFF_B2;
    __half* C2k = (__half*)(smc + OFF_C2);
    __half* P2t = (__half*)(smc + OFF_P2);

    int tid = threadIdx.x, lane = tid & 31, wid = tid >> 5;
    int q0 = blockIdx.x << 6, bh = blockIdx.y;
    int b = bh >> 4, h = bh & 15;
    const __half* Qg = g_Q + (size_t)bh * 65536;
    const __half* Kg = g_K + (size_t)bh * 65536;
    const __half* Vg = g_VT + (size_t)bh * 65536;
    const __half* PKg = g_PK + (size_t)h * 65536;
    const __half* PQg = g_PQ + (size_t)h * 65536;

    int lc = tid & 7, lr = tid >> 3;
    int g = lane >> 2, q2 = lane & 3;
    int wq0 = wid << 4;
    int qiA = wq0 + g, qiB = qiA + 8;

    __half* C2A = &C2k[qiA * CRW];
    __half* C2B = &C2k[qiB * CRW];
    __half* P2A = &P2t[(63 - qiA) * CW];
    __half* P2B = &P2t[(63 - qiB) * CW];

    /* preload G0: Q + K0 + V0 */
#pragma unroll
    for (int i = 0; i < 4; i++) {
        int r = lr + 16 * i;
        cp16(uQ + SW_OFF(r, lc), Qg + (size_t)(q0 + r) * 64 + lc * 8);
        cp16(sb + OFF_K0 + SW_OFF(r, lc), Kg + (size_t)r * 64 + lc * 8);
        cp16(sb + OFF_V0 + SW_OFF(r, lc), Vg + (size_t)r * 1024 + lc * 8);
    }
    cp_commit();
    /* preload G1: both 128-row bands for kt=0 */
    {
        int w01 = q0 + 449, w02 = 449 - q0;
#pragma unroll
        for (int i = 0; i < 8; i++) {
            int r = lr + 16 * i;
            int pv = w01 + r;
            cp16(uB1 + SW_OFF(pv & 127, lc), PKg + (size_t)min(max(pv, 0), 1023) * 64 + lc * 8);
            int pv2 = w02 + r;
            cp16(uB2 + SW_OFF(pv2 & 127, lc), PQg + (size_t)min(max(pv2, 0), 1023) * 64 + lc * 8);
        }
    }
    cp_commit();

    float O[8][4];
#pragma unroll
    for (int i = 0; i < 8; i++)
#pragma unroll
        for (int j = 0; j < 4; j++) O[i][j] = 0.f;
    float lA = 0.f, lB = 0.f;
    uint32_t aQ[4][4];

    for (int kt = 0; kt < 16; kt++) {
        int k0 = kt << 6;
        int w01 = q0 - k0 + 449;
        int w02 = k0 - q0 + 449;
        uint32_t uK = sb + ((kt & 1) ? OFF_K1 : OFF_K0);
        uint32_t uV = sb + ((kt & 1) ? OFF_V1 : OFF_V0);

        __syncthreads(); /* S0 */

        if (kt < 15) {
            uint32_t nK = sb + ((kt & 1) ? OFF_K0 : OFF_K1);
            uint32_t nV = sb + ((kt & 1) ? OFF_V0 : OFF_V1);
            int nk0 = k0 + 64;
#pragma unroll
            for (int i = 0; i < 4; i++) {
                int r = lr + 16 * i;
                cp16(nK + SW_OFF(r, lc), Kg + (size_t)(nk0 + r) * 64 + lc * 8);
                cp16(nV + SW_OFF(r, lc), Vg + (size_t)r * 1024 + nk0 + lc * 8);
            }
            cp_commit();
            cp_wait<1>();
        } else {
            cp_wait<0>();
        }
        __syncthreads(); /* S1 */

        if (kt == 0) {
#pragma unroll
            for (int ks = 0; ks < 4; ks++)
                ldsm4(aQ[ks], uQ + SW_OFF(wq0 + (lane & 15), ks * 2 + (lane >> 4)));
        }

        /* ---- c2p band mma ---- */
        {
            int npass = (kt == 0) ? 2 : 1;
            for (int pass = 0; pass < npass; pass++) {
                int npb = (kt == 0) ? pass * 4 : 0;
                float acc[8][4];
#pragma unroll
                for (int i = 0; i < 8; i++)
#pragma unroll
                    for (int j = 0; j < 4; j++) acc[i][j] = 0.f;
#pragma unroll
                for (int ks = 0; ks < 4; ks++) {
#pragma unroll
                    for (int np = 0; np < 4; np++) {
                        uint32_t bq[4];
                        int srow = (npb + np) * 16 + (((lane >> 4) & 1) << 3) + (lane & 7);
                        int slot = (w01 + srow) & 127;
                        ldsm4(bq, uB1 + SW_OFF(slot, ks * 2 + ((lane >> 3) & 1)));
                        mma16(acc[np * 2], aQ[ks], bq);
                        mma16(acc[np * 2 + 1], aQ[ks], bq + 2);
                    }
                }
#pragma unroll
                for (int f = 0; f < 8; f++) {
                    int col = npb * 16 + f * 8 + q2 * 2;
                    C2A[(k0 + 63 + qiA - col) & 127] = __float2half_rn(acc[f][0]);
                    C2A[(k0 + 62 + qiA - col) & 127] = __float2half_rn(acc[f][1]);
                    C2B[(k0 + 63 + qiB - col) & 127] = __float2half_rn(acc[f][2]);
                    C2B[(k0 + 62 + qiB - col) & 127] = __float2half_rn(acc[f][3]);
                }
            }
        }

        /* ---- p2c band mma: 5 ring groups; transposed store ---- */
        {
            float acc[10][4];
#pragma unroll
            for (int i = 0; i < 10; i++)
#pragma unroll
                for (int j = 0; j < 4; j++) acc[i][j] = 0.f;
#pragma unroll
            for (int ks = 0; ks < 4; ks++) {
                uint32_t a[4];
                ldsm4(a, uK + SW_OFF(wq0 + (lane & 15), ks * 2 + (lane >> 4)));
#pragma unroll
                for (int j = 0; j < 5; j++) {
                    uint32_t bq[4];
                    int srow = wq0 + j * 16 + (((lane >> 4) & 1) << 3) + (lane & 7);
                    int slot = (w02 + srow) & 127;
                    ldsm4(bq, uB2 + SW_OFF(slot, ks * 2 + ((lane >> 3) & 1)));
                    mma16(acc[j * 2], a, bq);
                    mma16(acc[j * 2 + 1], a, bq + 2);
                }
            }
#pragma unroll
            for (int f = 0; f < 10; f++) {
                int col = wq0 + (f >> 1) * 16 + (f & 1) * 8 + q2 * 2;
                int cA = col - qiA, cB = col - qiB;
                if ((unsigned)cA < 64u) P2t[cA * CW + qiA] = __float2half_rn(acc[f][0]);
                if ((unsigned)(cA + 1) < 64u) P2t[(cA + 1) * CW + qiA] = __float2half_rn(acc[f][1]);
                if ((unsigned)cB < 64u) P2t[cB * CW + qiB] = __float2half_rn(acc[f][2]);
                if ((unsigned)(cB + 1) < 64u) P2t[(cB + 1) * CW + qiB] = __float2half_rn(acc[f][3]);
            }
        }

        /* ---- QK mma ---- */
        float sS[8][4];
#pragma unroll
        for (int i = 0; i < 8; i++)
#pragma unroll
            for (int j = 0; j < 4; j++) sS[i][j] = 0.f;
#pragma unroll
        for (int ks = 0; ks < 4; ks++) {
#pragma unroll
            for (int np = 0; np < 4; np++) {
                uint32_t bq[4];
                int srow = np * 16 + (((lane >> 4) & 1) << 3) + (lane & 7);
                ldsm4(bq, uK + SW_OFF(srow, ks * 2 + ((lane >> 3) & 1)));
                mma16(sS[np * 2], aQ[ks], bq);
                mma16(sS[np * 2 + 1], aQ[ks], bq + 2);
            }
        }

        __syncthreads(); /* S2 */

        if (kt < 15) {
            int nw01 = w01 - 64;
            int nw02b = w02 + 128;
#pragma unroll
            for (int i = 0; i < 4; i++) {
                int r = lr + 16 * i;
                int pv = nw01 + r;
                cp16(uB1 + SW_OFF(pv & 127, lc), PKg + (size_t)min(max(pv, 0), 1023) * 64 + lc * 8);
                int pv2 = nw02b + r;
                cp16(uB2 + SW_OFF(pv2 & 127, lc), PQg + (size_t)min(max(pv2, 0), 1023) * 64 + lc * 8);
            }
            cp_commit();
        }

        /* ---- fixup (hadd2, hoisted bases) ---- */
#pragma unroll
        for (int nst = 0; nst < 8; nst++) {
            int kj = nst * 8 + q2 * 2;
            __half2 cA2 = __hadd2(*(__half2*)&C2A[(k0 + kj) & 127],
                                  *(__half2*)&P2A[kj]);
            __half2 cB2 = __hadd2(*(__half2*)&C2B[(k0 + kj) & 127],
                                  *(__half2*)&P2B[kj]);
            float2 fa = __half22float2(cA2);
            float2 fb = __half22float2(cB2);
            sS[nst][0] += fa.x;
            sS[nst][1] += fa.y;
            sS[nst][2] += fb.x;
            sS[nst][3] += fb.y;
        }

        /* ---- exp interleaved with PV mma ---- */
#pragma unroll
        for (int kc = 0; kc < 4; kc++) {
            uint32_t e[4];
            e[0] = ex2h2(sS[2 * kc][0], sS[2 * kc][1]);
            e[1] = ex2h2(sS[2 * kc][2], sS[2 * kc][3]);
            e[2] = ex2h2(sS[2 * kc + 1][0], sS[2 * kc + 1][1]);
            e[3] = ex2h2(sS[2 * kc + 1][2], sS[2 * kc + 1][3]);
            __half2 hA = __hadd2(*(__half2*)&e[0], *(__half2*)&e[2]);
            __half2 hB = __hadd2(*(__half2*)&e[1], *(__half2*)&e[3]);
            float2 fA = __half22float2(hA);
            float2 fB = __half22float2(hB);
            lA += fA.x + fA.y;
            lB += fB.x + fB.y;
#pragma unroll
            for (int np = 0; np < 4; np++) {
                uint32_t bq[4];
                int srow = np * 16 + (((lane >> 4) & 1) << 3) + (lane & 7);
                ldsm4(bq, uV + SW_OFF(srow, kc * 2 + ((lane >> 3) & 1)));
                mma16(O[np * 2], e, bq);
                mma16(O[np * 2 + 1], e, bq + 2);
            }
        }
    }

    /* ---- deferred l reduction + epilogue ---- */
    lA += __shfl_xor_sync(0xffffffffu, lA, 1, 4);
    lA += __shfl_xor_sync(0xffffffffu, lA, 2, 4);
    lB += __shfl_xor_sync(0xffffffffu, lB, 1, 4);
    lB += __shfl_xor_sync(0xffffffffu, lB, 2, 4);
    float invA = 1.f / lA, invB = 1.f / lB;
    __half* ctxA = &g_CTX[((size_t)(b * 1024) + q0 + qiA) * 1024 + h * 64 + q2 * 2];
    __half* ctxB = &g_CTX[((size_t)(b * 1024) + q0 + qiB) * 1024 + h * 64 + q2 * 2];
#pragma unroll
    for (int np = 0; np < 8; np++) {
        *(__half2*)&ctxA[np * 8] = __floats2half2_rn(O[np][0] * invA, O[np][1] * invA);
        *(__half2*)&ctxB[np * 8] = __floats2half2_rn(O[np][2] * invB, O[np][3] * invB);
    }
}

/* ---------------- LayerNorm ---------------- */
__global__ void __launch_bounds__(256) k_ln(const float* __restrict__ gam,
                                            const float* __restrict__ bet,
                                            float* __restrict__ out) {
    int m = blockIdx.x;
    int tid = threadIdx.x;
    const float* y = g_Y + (size_t)m * Hh;
    float4 v = *(const float4*)(y + (tid << 2));
    float s = v.x + v.y + v.z + v.w;
    float s2 = v.x * v.x + v.y * v.y + v.z * v.z + v.w * v.w;
#pragma unroll
    for (int o = 16; o; o >>= 1) {
        s += __shfl_xor_sync(0xffffffffu, s, o);
        s2 += __shfl_xor_sync(0xffffffffu, s2, o);
    }
    __shared__ float sh[8], sh2[8];
    int w = tid >> 5, ln = tid & 31;
    if (ln == 0) { sh[w] = s; sh2[w] = s2; }
    __syncthreads();
    s = 0.f; s2 = 0.f;
#pragma unroll
    for (int i = 0; i < 8; i++) { s += sh[i]; s2 += sh2[i]; }
    float mean = s * (1.0f / Hh);
    float var = s2 * (1.0f / Hh) - mean * mean;
    float inv = rsqrtf(var + 1e-7f);
    float4 g4 = *(const float4*)(gam + (tid << 2));
    float4 b4 = *(const float4*)(bet + (tid << 2));
    float4 o4;
    o4.x = g4.x * (v.x - mean) * inv + b4.x;
    o4.y = g4.y * (v.y - mean) * inv + b4.y;
    o4.z = g4.z * (v.z - mean) * inv + b4.z;
    o4.w = g4.w * (v.w - mean) * inv + b4.w;
    *(float4*)(out + (size_t)m * Hh + (tid << 2)) = o4;
}

/* ---------------- launch ---------------- */
extern "C" void kernel_launch(void* const* d_in, const int* in_sizes, int n_in,
                              void* d_out, int out_size) {
    const float* hs   = (const float*)d_in[0];
    const float* re   = (const float*)d_in[2];
    const float* w_in = (const float*)d_in[3];
    const float* qb   = (const float*)d_in[4];
    const float* vb   = (const float*)d_in[5];
    const float* w_pk = (const float*)d_in[6];
    const float* w_pq = (const float*)d_in[7];
    const float* b_pq = (const float*)d_in[8];
    const float* w_o  = (const float*)d_in[9];
    const float* b_o  = (const float*)d_in[10];
    const float* lng  = (const float*)d_in[11];
    const float* lnb  = (const float*)d_in[12];
    float* out = (float*)d_out;

    static int attr_set = 0;
    if (!attr_set) {
        cudaFuncSetAttribute(k_attn2, cudaFuncAttributeMaxDynamicSharedMemorySize, ATTN_SMEM);
        cudaFuncSetAttribute(gemm_all, cudaFuncAttributeMaxDynamicSharedMemorySize, GEMM_SMEM);
        attr_set = 1;
    }

    k_round2<<<5120, 256>>>(hs, re);                                        /* 1 */
    k_transp2<<<dim3(32, 32, 6), 256>>>(w_in, w_pk, w_pq, w_o, 0);          /* 2 */
    gemm_all<<<896, 256, GEMM_SMEM>>>(0, qb, vb, b_pq, b_o, hs);            /* 3 */
    k_attn2<<<dim3(16, 64), 128, ATTN_SMEM>>>();                            /* 4: profiled */
    gemm_all<<<256, 256, GEMM_SMEM>>>(4, qb, vb, b_pq, b_o, hs);            /* 5 */
    k_ln<<<4096, 256>>>(lng, lnb, out);                                     /* 6 */
}

// round 16
// speedup vs baseline: 1.0098x; 1.0098x over previous
#include <cuda_runtime.h>
#include <cuda_fp16.h>
#include <math.h>
#include <stdint.h>

#define Bb 4
#define Ss 1024
#define Hh 1024
#define NHh 16
#define Dd 64
#define Pp 1024

#define INV_SCALE 0.07216878364870322f
#define QSCALE (0.07216878364870322f * 1.4426950408889634f)

/* ------------------------- scratch (fp16 operands) ------------------------- */
__device__ __half g_Q[(size_t)Bb * NHh * Ss * Dd];
__device__ __half g_K[(size_t)Bb * NHh * Ss * Dd];
__device__ __half g_VT[(size_t)Bb * NHh * Dd * Ss];
__device__ __half g_PK[(size_t)NHh * Pp * Dd];
__device__ __half g_PQ[(size_t)NHh * Pp * Dd];
__device__ __half g_CTX[(size_t)Bb * Ss * Hh];
__device__ float  g_Y[(size_t)Bb * Ss * Hh];
__device__ __half g_HS[(size_t)Bb * Ss * Hh];
__device__ __half g_RE[(size_t)Pp * Hh];
__device__ __half g_WINT[(size_t)3 * Hh * Hh];
__device__ __half g_WPKT[(size_t)Hh * Hh];
__device__ __half g_WPQT[(size_t)Hh * Hh];
__device__ __half g_WOT[(size_t)Hh * Hh];

/* ------------------------- helpers ------------------------- */
__device__ __forceinline__ void cp16(uint32_t dst, const void* src) {
    asm volatile("cp.async.cg.shared.global [%0], [%1], 16;" :: "r"(dst), "l"(src));
}
__device__ __forceinline__ void cp_commit() { asm volatile("cp.async.commit_group;"); }
template <int N> __device__ __forceinline__ void cp_wait() {
    asm volatile("cp.async.wait_group %0;" :: "n"(N));
}
__device__ __forceinline__ void ldsm4(uint32_t a[4], uint32_t addr) {
    asm volatile("ldmatrix.sync.aligned.m8n8.x4.shared.b16 {%0,%1,%2,%3}, [%4];"
                 : "=r"(a[0]), "=r"(a[1]), "=r"(a[2]), "=r"(a[3]) : "r"(addr));
}
__device__ __forceinline__ void mma16(float c[4], const uint32_t a[4], const uint32_t b[2]) {
    asm volatile(
        "mma.sync.aligned.m16n8k16.row.col.f32.f16.f16.f32 "
        "{%0,%1,%2,%3}, {%4,%5,%6,%7}, {%8,%9}, {%0,%1,%2,%3};"
        : "+f"(c[0]), "+f"(c[1]), "+f"(c[2]), "+f"(c[3])
        : "r"(a[0]), "r"(a[1]), "r"(a[2]), "r"(a[3]), "r"(b[0]), "r"(b[1]));
}
__device__ __forceinline__ uint32_t ex2h2(float e0, float e1) {
    __half2 h = __floats2half2_rn(e0, e1);
    uint32_t u = *(uint32_t*)&h, o;
    asm("ex2.approx.f16x2 %0, %1;" : "=r"(o) : "r"(u));
    return o;
}

#define SW_OFF(row, c) ((((row) << 3) + ((c) ^ ((row) & 7))) << 4)

/* ------------------------- prep kernels ------------------------- */
__global__ void __launch_bounds__(256) k_round2(const float* __restrict__ hs,
                                                const float* __restrict__ re) {
    int bx = blockIdx.x;
    const float* src;
    __half* dst;
    size_t i;
    if (bx < 4096) { src = hs; dst = g_HS; i = ((size_t)bx * 256 + threadIdx.x) * 4; }
    else { src = re; dst = g_RE; i = ((size_t)(bx - 4096) * 256 + threadIdx.x) * 4; }
    float4 v = *(const float4*)(src + i);
    *(__half2*)(dst + i) = __floats2half2_rn(v.x, v.y);
    *(__half2*)(dst + i + 2) = __floats2half2_rn(v.z, v.w);
}

__global__ void __launch_bounds__(256) k_transp2(const float* __restrict__ w_in,
                                                 const float* __restrict__ w_pk,
                                                 const float* __restrict__ w_pq,
                                                 const float* __restrict__ w_o, int z0) {
    int z = z0 + blockIdx.z;
    const float* src;
    __half* dst;
    int N, nbase;
    if (z < 3) { src = w_in; dst = g_WINT; N = 3072; nbase = z * 1024; }
    else if (z == 3) { src = w_pk; dst = g_WPKT; N = 1024; nbase = 0; }
    else if (z == 4) { src = w_pq; dst = g_WPQT; N = 1024; nbase = 0; }
    else { src = w_o; dst = g_WOT; N = 1024; nbase = 0; }
    __shared__ float s[32][33];
    int n0 = nbase + (blockIdx.x << 5), k0 = blockIdx.y << 5;
    int tx = threadIdx.x & 31, ty = threadIdx.x >> 5;
#pragma unroll
    for (int j = 0; j < 4; j++)
        s[ty + j * 8][tx] = src[(size_t)(k0 + ty + j * 8) * N + n0 + tx];
    __syncthreads();
#pragma unroll
    for (int j = 0; j < 4; j++)
        dst[(size_t)(n0 + ty + j * 8) * 1024 + k0 + tx] = __float2half_rn(s[tx][ty + j * 8]);
}

/* ------------------------- fp16 GEMM, 128x128 block, 3-stage, x4 B-fragments ------------------------- */
#define STAGE_B 32768u
#define GEMM_SMEM 98304

__global__ void __launch_bounds__(256, 2) gemm_all(int which,
                                                   const float* __restrict__ qb,
                                                   const float* __restrict__ vb,
                                                   const float* __restrict__ bpq,
                                                   const float* __restrict__ bo,
                                                   const float* __restrict__ hs) {
    constexpr int NS = 16;
    int bx = blockIdx.x;
    int mode, z = 0, m0, n0;
    const __half *A, *B;
    if (which == 4) {
        mode = 4; A = g_CTX; B = g_WOT;
        n0 = (bx & 7) << 7; m0 = (bx >> 3) << 7;
    } else if (bx < 768) {
        mode = 0; A = g_HS; B = g_WINT;
        n0 = (bx % 24) << 7; m0 = (bx / 24) << 7;
    } else {
        mode = 1; int i = bx - 768; z = i >> 6; int j = i & 63;
        A = g_RE; B = z ? g_WPQT : g_WPKT;
        n0 = (j & 7) << 7; m0 = (j >> 3) << 7;
    }

    extern __shared__ char smemc[];
    uint32_t sbase = (uint32_t)__cvta_generic_to_shared(smemc);

    int tid = threadIdx.x;
    int lane = tid & 31, wid = tid >> 5;
    int wm = wid & 1, wn = wid >> 1;

    int kcopy = tid & 7, rsub = tid >> 3;
    const __half* asrc0 = A + (size_t)(m0 + rsub) * 1024 + kcopy * 8;
    const __half* bsrc0 = B + (size_t)(n0 + rsub) * 1024 + kcopy * 8;

    float c[4][4][4];
#pragma unroll
    for (int i = 0; i < 4; i++)
#pragma unroll
        for (int j = 0; j < 4; j++)
#pragma unroll
            for (int r = 0; r < 4; r++) c[i][j][r] = 0.f;

#define STAGE_COPY(slot, kofs)                                                       \
    {                                                                                \
        uint32_t sb = sbase + (slot) * STAGE_B;                                      \
        _Pragma("unroll") for (int it = 0; it < 4; it++) {                           \
            int row = it * 32 + rsub;                                                \
            cp16(sb + SW_OFF(row, kcopy), asrc0 + (size_t)it * 32 * 1024 + (kofs));  \
        }                                                                            \
        _Pragma("unroll") for (int it = 0; it < 4; it++) {                           \
            int row = it * 32 + rsub;                                                \
            cp16(sb + 16384u + SW_OFF(row, kcopy),                                   \
                 bsrc0 + (size_t)it * 32 * 1024 + (kofs));                           \
        }                                                                            \
        cp_commit();                                                                 \
    }

    STAGE_COPY(0, 0)
    STAGE_COPY(1, 64)

    int arow_l = wm * 64 + (lane & 15);
    int akhalf = lane >> 4;
    /* x4 B-fragment row base: lanes 0-15 -> stripe+0, lanes 16-31 -> stripe+8 */
    int brow4 = wn * 32 + (lane & 7) + (((lane >> 4) & 1) << 3);
    int bkhalf = (lane >> 3) & 1;

    int slot = 0;
    for (int s = 0; s < NS; s++) {
        if (s + 2 < NS) {
            int nslot = slot + 2; if (nslot >= 3) nslot -= 3;
            STAGE_COPY(nslot, (s + 2) * 64)
            cp_wait<2>();
        } else if (s + 1 < NS) {
            cp_wait<1>();
        } else {
            cp_wait<0>();
        }
        __syncthreads();

        uint32_t sA = sbase + slot * STAGE_B;
        uint32_t sB = sA + 16384u;

#pragma unroll
        for (int kc = 0; kc < 4; kc++) {
            uint32_t bf[2][4];
#pragma unroll
            for (int p = 0; p < 2; p++)
                ldsm4(bf[p], sB + SW_OFF(brow4 + p * 16, kc * 2 + bkhalf));
#pragma unroll
            for (int st = 0; st < 4; st++) {
                uint32_t af[4];
                ldsm4(af, sA + SW_OFF(arow_l + st * 16, kc * 2 + akhalf));
#pragma unroll
                for (int p = 0; p < 2; p++) {
                    mma16(c[st][p * 2], af, bf[p]);
                    mma16(c[st][p * 2 + 1], af, bf[p] + 2);
                }
            }
        }
        __syncthreads();
        if (++slot == 3) slot = 0;
    }

    int g = lane >> 2, q2 = lane & 3;
    int mbt = m0 + wm * 64, nbt = n0 + wn * 32;
#pragma unroll
    for (int st = 0; st < 4; st++) {
#pragma unroll
        for (int nst = 0; nst < 4; nst++) {
#pragma unroll
            for (int half = 0; half < 2; half++) {
                int m = mbt + st * 16 + g + half * 8;
                int n = nbt + nst * 8 + q2 * 2;
                float v0 = c[st][nst][half * 2 + 0];
                float v1 = c[st][nst][half * 2 + 1];
                if (mode == 0) {
                    int h = n / 192, rem = n - h * 192;
                    int t = rem >> 6, d = rem & 63;
                    int bq = m >> 10, srow = m & 1023;
                    size_t idx = (((size_t)(bq * 16 + h)) * 1024 + srow) * 64 + d;
                    if (t == 0) {
                        *(__half2*)&g_Q[idx] = __floats2half2_rn(
                            (v0 + qb[h * 64 + d]) * QSCALE,
                            (v1 + qb[h * 64 + d + 1]) * QSCALE);
                    } else if (t == 1) {
                        *(__half2*)&g_K[idx] = __floats2half2_rn(v0, v1);
                    } else {
                        size_t vt = (((size_t)(bq * 16 + h)) * 64 + d) * 1024 + srow;
                        g_VT[vt] = __float2half_rn(v0 + vb[h * 64 + d]);
                        g_VT[vt + 1024] = __float2half_rn(v1 + vb[h * 64 + d + 1]);
                    }
                } else if (mode == 1) {
                    int h = n >> 6, d = n & 63;
                    size_t idx = ((size_t)h * 1024 + m) * 64 + d;
                    if (z == 0) {
                        *(__half2*)&g_PK[idx] = __floats2half2_rn(v0, v1);
                    } else {
                        *(__half2*)&g_PQ[idx] = __floats2half2_rn(
                            (v0 + bpq[n]) * QSCALE, (v1 + bpq[n + 1]) * QSCALE);
                    }
                } else {
                    size_t o = (size_t)m * 1024 + n;
                    g_Y[o] = v0 + bo[n] + hs[o];
                    g_Y[o + 1] = v1 + bo[n + 1] + hs[o + 1];
                }
            }
        }
    }
#undef STAGE_COPY
}

/* ---------------- fused attention: padded P2t (unconditional stores) ----
 * SMEM: Q@0(8K) K0@8K K1@16K V0@24K V1@32K B1@40K(16K) B2@56K(16K)
 *       C2k@73728(64*136*2=17408) P2pad@91136(96*72*2=13824). total 104960.
 * P2pad row = (col - qi) + 16; valid reads rows [16, 80).
 */
#define CW 72
#define CRW 136
#define OFF_K0 8192u
#define OFF_K1 16384u
#define OFF_V0 24576u
#define OFF_V1 32768u
#define OFF_B1 40960u
#define OFF_B2 57344u
#define OFF_C2 73728u
#define OFF_P2 91136u
#define ATTN_SMEM 104960

__global__ void __launch_bounds__(128, 2) k_attn2() {
    extern __shared__ char smc[];
    uint32_t sb = (uint32_t)__cvta_generic_to_shared(smc);
    const uint32_t uQ = sb;
    const uint32_t uB1 = sb + OFF_B1;
    const uint32_t uB2 = sb + OFF_B2;
    __half* C2k = (__half*)(smc + OFF_C2);
    __half* P2p = (__half*)(smc + OFF_P2);   /* padded: row = (col-qi)+16 */

    int tid = threadIdx.x, lane = tid & 31, wid = tid >> 5;
    int q0 = blockIdx.x << 6, bh = blockIdx.y;
    int b = bh >> 4, h = bh & 15;
    const __half* Qg = g_Q + (size_t)bh * 65536;
    const __half* Kg = g_K + (size_t)bh * 65536;
    const __half* Vg = g_VT + (size_t)bh * 65536;
    const __half* PKg = g_PK + (size_t)h * 65536;
    const __half* PQg = g_PQ + (size_t)h * 65536;

    int lc = tid & 7, lr = tid >> 3;
    int g = lane >> 2, q2 = lane & 3;
    int wq0 = wid << 4;
    int qiA = wq0 + g, qiB = qiA + 8;

    __half* C2A = &C2k[qiA * CRW];
    __half* C2B = &C2k[qiB * CRW];
    __half* P2A = &P2p[(63 - qiA + 16) * CW];
    __half* P2B = &P2p[(63 - qiB + 16) * CW];

    /* preload G0: Q + K0 + V0 */
#pragma unroll
    for (int i = 0; i < 4; i++) {
        int r = lr + 16 * i;
        cp16(uQ + SW_OFF(r, lc), Qg + (size_t)(q0 + r) * 64 + lc * 8);
        cp16(sb + OFF_K0 + SW_OFF(r, lc), Kg + (size_t)r * 64 + lc * 8);
        cp16(sb + OFF_V0 + SW_OFF(r, lc), Vg + (size_t)r * 1024 + lc * 8);
    }
    cp_commit();
    /* preload G1: both 128-row bands for kt=0 */
    {
        int w01 = q0 + 449, w02 = 449 - q0;
#pragma unroll
        for (int i = 0; i < 8; i++) {
            int r = lr + 16 * i;
            int pv = w01 + r;
            cp16(uB1 + SW_OFF(pv & 127, lc), PKg + (size_t)min(max(pv, 0), 1023) * 64 + lc * 8);
            int pv2 = w02 + r;
            cp16(uB2 + SW_OFF(pv2 & 127, lc), PQg + (size_t)min(max(pv2, 0), 1023) * 64 + lc * 8);
        }
    }
    cp_commit();

    float O[8][4];
#pragma unroll
    for (int i = 0; i < 8; i++)
#pragma unroll
        for (int j = 0; j < 4; j++) O[i][j] = 0.f;
    float lA = 0.f, lB = 0.f;
    uint32_t aQ[4][4];

    for (int kt = 0; kt < 16; kt++) {
        int k0 = kt << 6;
        int w01 = q0 - k0 + 449;
        int w02 = k0 - q0 + 449;
        uint32_t uK = sb + ((kt & 1) ? OFF_K1 : OFF_K0);
        uint32_t uV = sb + ((kt & 1) ? OFF_V1 : OFF_V0);

        __syncthreads(); /* S0 */

        if (kt < 15) {
            uint32_t nK = sb + ((kt & 1) ? OFF_K0 : OFF_K1);
            uint32_t nV = sb + ((kt & 1) ? OFF_V0 : OFF_V1);
            int nk0 = k0 + 64;
#pragma unroll
            for (int i = 0; i < 4; i++) {
                int r = lr + 16 * i;
                cp16(nK + SW_OFF(r, lc), Kg + (size_t)(nk0 + r) * 64 + lc * 8);
                cp16(nV + SW_OFF(r, lc), Vg + (size_t)r * 1024 + nk0 + lc * 8);
            }
            cp_commit();
            cp_wait<1>();
        } else {
            cp_wait<0>();
        }
        __syncthreads(); /* S1 */

        if (kt == 0) {
#pragma unroll
            for (int ks = 0; ks < 4; ks++)
                ldsm4(aQ[ks], uQ + SW_OFF(wq0 + (lane & 15), ks * 2 + (lane >> 4)));
        }

        /* ---- c2p band mma ---- */
        {
            int npass = (kt == 0) ? 2 : 1;
            for (int pass = 0; pass < npass; pass++) {
                int npb = (kt == 0) ? pass * 4 : 0;
                float acc[8][4];
#pragma unroll
                for (int i = 0; i < 8; i++)
#pragma unroll
                    for (int j = 0; j < 4; j++) acc[i][j] = 0.f;
#pragma unroll
                for (int ks = 0; ks < 4; ks++) {
#pragma unroll
                    for (int np = 0; np < 4; np++) {
                        uint32_t bq[4];
                        int srow = (npb + np) * 16 + (((lane >> 4) & 1) << 3) + (lane & 7);
                        int slot = (w01 + srow) & 127;
                        ldsm4(bq, uB1 + SW_OFF(slot, ks * 2 + ((lane >> 3) & 1)));
                        mma16(acc[np * 2], aQ[ks], bq);
                        mma16(acc[np * 2 + 1], aQ[ks], bq + 2);
                    }
                }
#pragma unroll
                for (int f = 0; f < 8; f++) {
                    int col = npb * 16 + f * 8 + q2 * 2;
                    C2A[(k0 + 63 + qiA - col) & 127] = __float2half_rn(acc[f][0]);
                    C2A[(k0 + 62 + qiA - col) & 127] = __float2half_rn(acc[f][1]);
                    C2B[(k0 + 63 + qiB - col) & 127] = __float2half_rn(acc[f][2]);
                    C2B[(k0 + 62 + qiB - col) & 127] = __float2half_rn(acc[f][3]);
                }
            }
        }

        /* ---- p2c band mma: 5 ring groups; unconditional padded stores ---- */
        {
            float acc[10][4];
#pragma unroll
            for (int i = 0; i < 10; i++)
#pragma unroll
                for (int j = 0; j < 4; j++) acc[i][j] = 0.f;
#pragma unroll
            for (int ks = 0; ks < 4; ks++) {
                uint32_t a[4];
                ldsm4(a, uK + SW_OFF(wq0 + (lane & 15), ks * 2 + (lane >> 4)));
#pragma unroll
                for (int j = 0; j < 5; j++) {
                    uint32_t bq[4];
                    int srow = wq0 + j * 16 + (((lane >> 4) & 1) << 3) + (lane & 7);
                    int slot = (w02 + srow) & 127;
                    ldsm4(bq, uB2 + SW_OFF(slot, ks * 2 + ((lane >> 3) & 1)));
                    mma16(acc[j * 2], a, bq);
                    mma16(acc[j * 2 + 1], a, bq + 2);
                }
            }
#pragma unroll
            for (int f = 0; f < 10; f++) {
                int col = wq0 + (f >> 1) * 16 + (f & 1) * 8 + q2 * 2;
                int rA = col - qiA + 16, rB = col - qiB + 16;
                P2p[rA * CW + qiA] = __float2half_rn(acc[f][0]);
                P2p[(rA + 1) * CW + qiA] = __float2half_rn(acc[f][1]);
                P2p[rB * CW + qiB] = __float2half_rn(acc[f][2]);
                P2p[(rB + 1) * CW + qiB] = __float2half_rn(acc[f][3]);
            }
        }

        /* ---- QK mma ---- */
        float sS[8][4];
#pragma unroll
        for (int i = 0; i < 8; i++)
#pragma unroll
            for (int j = 0; j < 4; j++) sS[i][j] = 0.f;
#pragma unroll
        for (int ks = 0; ks < 4; ks++) {
#pragma unroll
            for (int np = 0; np < 4; np++) {
                uint32_t bq[4];
                int srow = np * 16 + (((lane >> 4) & 1) << 3) + (lane & 7);
                ldsm4(bq, uK + SW_OFF(srow, ks * 2 + ((lane >> 3) & 1)));
                mma16(sS[np * 2], aQ[ks], bq);
                mma16(sS[np * 2 + 1], aQ[ks], bq + 2);
            }
        }

        __syncthreads(); /* S2 */

        if (kt < 15) {
            int nw01 = w01 - 64;
            int nw02b = w02 + 128;
#pragma unroll
            for (int i = 0; i < 4; i++) {
                int r = lr + 16 * i;
                int pv = nw01 + r;
                cp16(uB1 + SW_OFF(pv & 127, lc), PKg + (size_t)min(max(pv, 0), 1023) * 64 + lc * 8);
                int pv2 = nw02b + r;
                cp16(uB2 + SW_OFF(pv2 & 127, lc), PQg + (size_t)min(max(pv2, 0), 1023) * 64 + lc * 8);
            }
            cp_commit();
        }

        /* ---- fixup (hadd2, hoisted bases) ---- */
#pragma unroll
        for (int nst = 0; nst < 8; nst++) {
            int kj = nst * 8 + q2 * 2;
            __half2 cA2 = __hadd2(*(__half2*)&C2A[(k0 + kj) & 127],
                                  *(__half2*)&P2A[kj]);
            __half2 cB2 = __hadd2(*(__half2*)&C2B[(k0 + kj) & 127],
                                  *(__half2*)&P2B[kj]);
            float2 fa = __half22float2(cA2);
            float2 fb = __half22float2(cB2);
            sS[nst][0] += fa.x;
            sS[nst][1] += fa.y;
            sS[nst][2] += fb.x;
            sS[nst][3] += fb.y;
        }

        /* ---- exp interleaved with PV mma ---- */
#pragma unroll
        for (int kc = 0; kc < 4; kc++) {
            uint32_t e[4];
            e[0] = ex2h2(sS[2 * kc][0], sS[2 * kc][1]);
            e[1] = ex2h2(sS[2 * kc][2], sS[2 * kc][3]);
            e[2] = ex2h2(sS[2 * kc + 1][0], sS[2 * kc + 1][1]);
            e[3] = ex2h2(sS[2 * kc + 1][2], sS[2 * kc + 1][3]);
            __half2 hA = __hadd2(*(__half2*)&e[0], *(__half2*)&e[2]);
            __half2 hB = __hadd2(*(__half2*)&e[1], *(__half2*)&e[3]);
            float2 fA = __half22float2(hA);
            float2 fB = __half22float2(hB);
            lA += fA.x + fA.y;
            lB += fB.x + fB.y;
#pragma unroll
            for (int np = 0; np < 4; np++) {
                uint32_t bq[4];
                int srow = np * 16 + (((lane >> 4) & 1) << 3) + (lane & 7);
                ldsm4(bq, uV + SW_OFF(srow, kc * 2 + ((lane >> 3) & 1)));
                mma16(O[np * 2], e, bq);
                mma16(O[np * 2 + 1], e, bq + 2);
            }
        }
    }

    /* ---- deferred l reduction + epilogue ---- */
    lA += __shfl_xor_sync(0xffffffffu, lA, 1, 4);
    lA += __shfl_xor_sync(0xffffffffu, lA, 2, 4);
    lB += __shfl_xor_sync(0xffffffffu, lB, 1, 4);
    lB += __shfl_xor_sync(0xffffffffu, lB, 2, 4);
    float invA = 1.f / lA, invB = 1.f / lB;
    __half* ctxA = &g_CTX[((size_t)(b * 1024) + q0 + qiA) * 1024 + h * 64 + q2 * 2];
    __half* ctxB = &g_CTX[((size_t)(b * 1024) + q0 + qiB) * 1024 + h * 64 + q2 * 2];
#pragma unroll
    for (int np = 0; np < 8; np++) {
        *(__half2*)&ctxA[np * 8] = __floats2half2_rn(O[np][0] * invA, O[np][1] * invA);
        *(__half2*)&ctxB[np * 8] = __floats2half2_rn(O[np][2] * invB, O[np][3] * invB);
    }
}

/* ---------------- LayerNorm ---------------- */
__global__ void __launch_bounds__(256) k_ln(const float* __restrict__ gam,
                                            const float* __restrict__ bet,
                                            float* __restrict__ out) {
    int m = blockIdx.x;
    int tid = threadIdx.x;
    const float* y = g_Y + (size_t)m * Hh;
    float4 v = *(const float4*)(y + (tid << 2));
    float s = v.x + v.y + v.z + v.w;
    float s2 = v.x * v.x + v.y * v.y + v.z * v.z + v.w * v.w;
#pragma unroll
    for (int o = 16; o; o >>= 1) {
        s += __shfl_xor_sync(0xffffffffu, s, o);
        s2 += __shfl_xor_sync(0xffffffffu, s2, o);
    }
    __shared__ float sh[8], sh2[8];
    int w = tid >> 5, ln = tid & 31;
    if (ln == 0) { sh[w] = s; sh2[w] = s2; }
    __syncthreads();
    s = 0.f; s2 = 0.f;
#pragma unroll
    for (int i = 0; i < 8; i++) { s += sh[i]; s2 += sh2[i]; }
    float mean = s * (1.0f / Hh);
    float var = s2 * (1.0f / Hh) - mean * mean;
    float inv = rsqrtf(var + 1e-7f);
    float4 g4 = *(const float4*)(gam + (tid << 2));
    float4 b4 = *(const float4*)(bet + (tid << 2));
    float4 o4;
    o4.x = g4.x * (v.x - mean) * inv + b4.x;
    o4.y = g4.y * (v.y - mean) * inv + b4.y;
    o4.z = g4.z * (v.z - mean) * inv + b4.z;
    o4.w = g4.w * (v.w - mean) * inv + b4.w;
    *(float4*)(out + (size_t)m * Hh + (tid << 2)) = o4;
}

/* ---------------- launch ---------------- */
extern "C" void kernel_launch(void* const* d_in, const int* in_sizes, int n_in,
                              void* d_out, int out_size) {
    const float* hs   = (const float*)d_in[0];
    const float* re   = (const float*)d_in[2];
    const float* w_in = (const float*)d_in[3];
    const float* qb   = (const float*)d_in[4];
    const float* vb   = (const float*)d_in[5];
    const float* w_pk = (const float*)d_in[6];
    const float* w_pq = (const float*)d_in[7];
    const float* b_pq = (const float*)d_in[8];
    const float* w_o  = (const float*)d_in[9];
    const float* b_o  = (const float*)d_in[10];
    const float* lng  = (const float*)d_in[11];
    const float* lnb  = (const float*)d_in[12];
    float* out = (float*)d_out;

    static int attr_set = 0;
    if (!attr_set) {
        cudaFuncSetAttribute(k_attn2, cudaFuncAttributeMaxDynamicSharedMemorySize, ATTN_SMEM);
        cudaFuncSetAttribute(gemm_all, cudaFuncAttributeMaxDynamicSharedMemorySize, GEMM_SMEM);
        attr_set = 1;
    }

    k_round2<<<5120, 256>>>(hs, re);                                        /* 1 */
    k_transp2<<<dim3(32, 32, 6), 256>>>(w_in, w_pk, w_pq, w_o, 0);          /* 2 */
    gemm_all<<<896, 256, GEMM_SMEM>>>(0, qb, vb, b_pq, b_o, hs);            /* 3 */
    k_attn2<<<dim3(16, 64), 128, ATTN_SMEM>>>();                            /* 4: profiled */
    gemm_all<<<256, 256, GEMM_SMEM>>>(4, qb, vb, b_pq, b_o, hs);            /* 5 */
    k_ln<<<4096, 256>>>(lng, lnb, out);                                     /* 6 */
}

// round 17
// speedup vs baseline: 1.0225x; 1.0125x over previous
#include <cuda_runtime.h>
#include <cuda_fp16.h>
#include <math.h>
#include <stdint.h>

#define Bb 4
#define Ss 1024
#define Hh 1024
#define NHh 16
#define Dd 64
#define Pp 1024

#define INV_SCALE 0.07216878364870322f
#define QSCALE (0.07216878364870322f * 1.4426950408889634f)

/* ------------------------- scratch (fp16 operands) ------------------------- */
__device__ __half g_Q[(size_t)Bb * NHh * Ss * Dd];
__device__ __half g_K[(size_t)Bb * NHh * Ss * Dd];
__device__ __half g_VT[(size_t)Bb * NHh * Dd * Ss];
__device__ __half g_PK[(size_t)NHh * Pp * Dd];
__device__ __half g_PQ[(size_t)NHh * Pp * Dd];
__device__ __half g_CTX[(size_t)Bb * Ss * Hh];
__device__ float  g_Y[(size_t)Bb * Ss * Hh];
__device__ __half g_HS[(size_t)Bb * Ss * Hh];
__device__ __half g_RE[(size_t)Pp * Hh];
__device__ __half g_WINT[(size_t)3 * Hh * Hh];
__device__ __half g_WPKT[(size_t)Hh * Hh];
__device__ __half g_WPQT[(size_t)Hh * Hh];
__device__ __half g_WOT[(size_t)Hh * Hh];

/* ------------------------- helpers ------------------------- */
__device__ __forceinline__ void cp16(uint32_t dst, const void* src) {
    asm volatile("cp.async.cg.shared.global [%0], [%1], 16;" :: "r"(dst), "l"(src));
}
__device__ __forceinline__ void cp_commit() { asm volatile("cp.async.commit_group;"); }
template <int N> __device__ __forceinline__ void cp_wait() {
    asm volatile("cp.async.wait_group %0;" :: "n"(N));
}
__device__ __forceinline__ void ldsm4(uint32_t a[4], uint32_t addr) {
    asm volatile("ldmatrix.sync.aligned.m8n8.x4.shared.b16 {%0,%1,%2,%3}, [%4];"
                 : "=r"(a[0]), "=r"(a[1]), "=r"(a[2]), "=r"(a[3]) : "r"(addr));
}
__device__ __forceinline__ void mma16(float c[4], const uint32_t a[4], const uint32_t b[2]) {
    asm volatile(
        "mma.sync.aligned.m16n8k16.row.col.f32.f16.f16.f32 "
        "{%0,%1,%2,%3}, {%4,%5,%6,%7}, {%8,%9}, {%0,%1,%2,%3};"
        : "+f"(c[0]), "+f"(c[1]), "+f"(c[2]), "+f"(c[3])
        : "r"(a[0]), "r"(a[1]), "r"(a[2]), "r"(a[3]), "r"(b[0]), "r"(b[1]));
}
__device__ __forceinline__ uint32_t ex2h2(float e0, float e1) {
    __half2 h = __floats2half2_rn(e0, e1);
    uint32_t u = *(uint32_t*)&h, o;
    asm("ex2.approx.f16x2 %0, %1;" : "=r"(o) : "r"(u));
    return o;
}

#define SW_OFF(row, c) ((((row) << 3) + ((c) ^ ((row) & 7))) << 4)

/* ------------------------- prep kernels ------------------------- */
__global__ void __launch_bounds__(256) k_round2(const float* __restrict__ hs,
                                                const float* __restrict__ re) {
    int bx = blockIdx.x;
    const float* src;
    __half* dst;
    size_t i;
    if (bx < 4096) { src = hs; dst = g_HS; i = ((size_t)bx * 256 + threadIdx.x) * 4; }
    else { src = re; dst = g_RE; i = ((size_t)(bx - 4096) * 256 + threadIdx.x) * 4; }
    float4 v = *(const float4*)(src + i);
    *(__half2*)(dst + i) = __floats2half2_rn(v.x, v.y);
    *(__half2*)(dst + i + 2) = __floats2half2_rn(v.z, v.w);
}

__global__ void __launch_bounds__(256) k_transp2(const float* __restrict__ w_in,
                                                 const float* __restrict__ w_pk,
                                                 const float* __restrict__ w_pq,
                                                 const float* __restrict__ w_o, int z0) {
    int z = z0 + blockIdx.z;
    const float* src;
    __half* dst;
    int N, nbase;
    if (z < 3) { src = w_in; dst = g_WINT; N = 3072; nbase = z * 1024; }
    else if (z == 3) { src = w_pk; dst = g_WPKT; N = 1024; nbase = 0; }
    else if (z == 4) { src = w_pq; dst = g_WPQT; N = 1024; nbase = 0; }
    else { src = w_o; dst = g_WOT; N = 1024; nbase = 0; }
    __shared__ float s[32][33];
    int n0 = nbase + (blockIdx.x << 5), k0 = blockIdx.y << 5;
    int tx = threadIdx.x & 31, ty = threadIdx.x >> 5;
#pragma unroll
    for (int j = 0; j < 4; j++)
        s[ty + j * 8][tx] = src[(size_t)(k0 + ty + j * 8) * N + n0 + tx];
    __syncthreads();
#pragma unroll
    for (int j = 0; j < 4; j++)
        dst[(size_t)(n0 + ty + j * 8) * 1024 + k0 + tx] = __float2half_rn(s[tx][ty + j * 8]);
}

/* ------------------------- fp16 GEMM, 128x128 block, 3-stage, x4 B-fragments ------------------------- */
#define STAGE_B 32768u
#define GEMM_SMEM 98304

__global__ void __launch_bounds__(256, 2) gemm_all(int which,
                                                   const float* __restrict__ qb,
                                                   const float* __restrict__ vb,
                                                   const float* __restrict__ bpq,
                                                   const float* __restrict__ bo,
                                                   const float* __restrict__ hs) {
    constexpr int NS = 16;
    int bx = blockIdx.x;
    int mode, z = 0, m0, n0;
    const __half *A, *B;
    if (which == 4) {
        mode = 4; A = g_CTX; B = g_WOT;
        n0 = (bx & 7) << 7; m0 = (bx >> 3) << 7;
    } else if (bx < 768) {
        mode = 0; A = g_HS; B = g_WINT;
        n0 = (bx % 24) << 7; m0 = (bx / 24) << 7;
    } else {
        mode = 1; int i = bx - 768; z = i >> 6; int j = i & 63;
        A = g_RE; B = z ? g_WPQT : g_WPKT;
        n0 = (j & 7) << 7; m0 = (j >> 3) << 7;
    }

    extern __shared__ char smemc[];
    uint32_t sbase = (uint32_t)__cvta_generic_to_shared(smemc);

    int tid = threadIdx.x;
    int lane = tid & 31, wid = tid >> 5;
    int wm = wid & 1, wn = wid >> 1;

    int kcopy = tid & 7, rsub = tid >> 3;
    const __half* asrc0 = A + (size_t)(m0 + rsub) * 1024 + kcopy * 8;
    const __half* bsrc0 = B + (size_t)(n0 + rsub) * 1024 + kcopy * 8;

    float c[4][4][4];
#pragma unroll
    for (int i = 0; i < 4; i++)
#pragma unroll
        for (int j = 0; j < 4; j++)
#pragma unroll
            for (int r = 0; r < 4; r++) c[i][j][r] = 0.f;

#define STAGE_COPY(slot, kofs)                                                       \
    {                                                                                \
        uint32_t sb = sbase + (slot) * STAGE_B;                                      \
        _Pragma("unroll") for (int it = 0; it < 4; it++) {                           \
            int row = it * 32 + rsub;                                                \
            cp16(sb + SW_OFF(row, kcopy), asrc0 + (size_t)it * 32 * 1024 + (kofs));  \
        }                                                                            \
        _Pragma("unroll") for (int it = 0; it < 4; it++) {                           \
            int row = it * 32 + rsub;                                                \
            cp16(sb + 16384u + SW_OFF(row, kcopy),                                   \
                 bsrc0 + (size_t)it * 32 * 1024 + (kofs));                           \
        }                                                                            \
        cp_commit();                                                                 \
    }

    STAGE_COPY(0, 0)
    STAGE_COPY(1, 64)

    int arow_l = wm * 64 + (lane & 15);
    int akhalf = lane >> 4;
    int brow4 = wn * 32 + (lane & 7) + (((lane >> 4) & 1) << 3);
    int bkhalf = (lane >> 3) & 1;

    int slot = 0;
    for (int s = 0; s < NS; s++) {
        if (s + 2 < NS) {
            int nslot = slot + 2; if (nslot >= 3) nslot -= 3;
            STAGE_COPY(nslot, (s + 2) * 64)
            cp_wait<2>();
        } else if (s + 1 < NS) {
            cp_wait<1>();
        } else {
            cp_wait<0>();
        }
        __syncthreads();

        uint32_t sA = sbase + slot * STAGE_B;
        uint32_t sB = sA + 16384u;

#pragma unroll
        for (int kc = 0; kc < 4; kc++) {
            uint32_t bf[2][4];
#pragma unroll
            for (int p = 0; p < 2; p++)
                ldsm4(bf[p], sB + SW_OFF(brow4 + p * 16, kc * 2 + bkhalf));
#pragma unroll
            for (int st = 0; st < 4; st++) {
                uint32_t af[4];
                ldsm4(af, sA + SW_OFF(arow_l + st * 16, kc * 2 + akhalf));
#pragma unroll
                for (int p = 0; p < 2; p++) {
                    mma16(c[st][p * 2], af, bf[p]);
                    mma16(c[st][p * 2 + 1], af, bf[p] + 2);
                }
            }
        }
        __syncthreads();
        if (++slot == 3) slot = 0;
    }

    int g = lane >> 2, q2 = lane & 3;
    int mbt = m0 + wm * 64, nbt = n0 + wn * 32;
#pragma unroll
    for (int st = 0; st < 4; st++) {
#pragma unroll
        for (int nst = 0; nst < 4; nst++) {
#pragma unroll
            for (int half = 0; half < 2; half++) {
                int m = mbt + st * 16 + g + half * 8;
                int n = nbt + nst * 8 + q2 * 2;
                float v0 = c[st][nst][half * 2 + 0];
                float v1 = c[st][nst][half * 2 + 1];
                if (mode == 0) {
                    int h = n / 192, rem = n - h * 192;
                    int t = rem >> 6, d = rem & 63;
                    int bq = m >> 10, srow = m & 1023;
                    size_t idx = (((size_t)(bq * 16 + h)) * 1024 + srow) * 64 + d;
                    if (t == 0) {
                        *(__half2*)&g_Q[idx] = __floats2half2_rn(
                            (v0 + qb[h * 64 + d]) * QSCALE,
                            (v1 + qb[h * 64 + d + 1]) * QSCALE);
                    } else if (t == 1) {
                        *(__half2*)&g_K[idx] = __floats2half2_rn(v0, v1);
                    } else {
                        size_t vt = (((size_t)(bq * 16 + h)) * 64 + d) * 1024 + srow;
                        g_VT[vt] = __float2half_rn(v0 + vb[h * 64 + d]);
                        g_VT[vt + 1024] = __float2half_rn(v1 + vb[h * 64 + d + 1]);
                    }
                } else if (mode == 1) {
                    int h = n >> 6, d = n & 63;
                    size_t idx = ((size_t)h * 1024 + m) * 64 + d;
                    if (z == 0) {
                        *(__half2*)&g_PK[idx] = __floats2half2_rn(v0, v1);
                    } else {
                        *(__half2*)&g_PQ[idx] = __floats2half2_rn(
                            (v0 + bpq[n]) * QSCALE, (v1 + bpq[n + 1]) * QSCALE);
                    }
                } else {
                    size_t o = (size_t)m * 1024 + n;
                    g_Y[o] = v0 + bo[n] + hs[o];
                    g_Y[o + 1] = v1 + bo[n + 1] + hs[o + 1];
                }
            }
        }
    }
#undef STAGE_COPY
}

/* ---------------- fused attention: R16 + half2 l-accum + hoisted frag offsets ----
 * SMEM: Q@0(8K) K0@8K K1@16K V0@24K V1@32K B1@40K(16K) B2@56K(16K)
 *       C2k@73728(17408) P2pad@91136(96*72*2=13824). total 104960. 2 CTAs/SM.
 */
#define CW 72
#define CRW 136
#define OFF_K0 8192u
#define OFF_K1 16384u
#define OFF_V0 24576u
#define OFF_V1 32768u
#define OFF_B1 40960u
#define OFF_B2 57344u
#define OFF_C2 73728u
#define OFF_P2 91136u
#define ATTN_SMEM 104960

__global__ void __launch_bounds__(128, 2) k_attn2() {
    extern __shared__ char smc[];
    uint32_t sb = (uint32_t)__cvta_generic_to_shared(smc);
    const uint32_t uQ = sb;
    const uint32_t uB1 = sb + OFF_B1;
    const uint32_t uB2 = sb + OFF_B2;
    __half* C2k = (__half*)(smc + OFF_C2);
    __half* P2p = (__half*)(smc + OFF_P2);

    int tid = threadIdx.x, lane = tid & 31, wid = tid >> 5;
    int q0 = blockIdx.x << 6, bh = blockIdx.y;
    int b = bh >> 4, h = bh & 15;
    const __half* Qg = g_Q + (size_t)bh * 65536;
    const __half* Kg = g_K + (size_t)bh * 65536;
    const __half* Vg = g_VT + (size_t)bh * 65536;
    const __half* PKg = g_PK + (size_t)h * 65536;
    const __half* PQg = g_PQ + (size_t)h * 65536;

    int lc = tid & 7, lr = tid >> 3;
    int g = lane >> 2, q2 = lane & 3;
    int wq0 = wid << 4;
    int qiA = wq0 + g, qiB = qiA + 8;

    __half* C2A = &C2k[qiA * CRW];
    __half* C2B = &C2k[qiB * CRW];
    __half* P2A = &P2p[(63 - qiA + 16) * CW];
    __half* P2B = &P2p[(63 - qiB + 16) * CW];

    /* hoisted fragment-row pieces (loop-invariant) */
    int fr_row = (((lane >> 4) & 1) << 3) + (lane & 7);   /* srow low part */
    int fr_khb = (lane >> 3) & 1;                          /* k-half bit   */
    int aw_row = wq0 + (lane & 15);                        /* A-frag row   */

    /* preload G0: Q + K0 + V0 */
#pragma unroll
    for (int i = 0; i < 4; i++) {
        int r = lr + 16 * i;
        cp16(uQ + SW_OFF(r, lc), Qg + (size_t)(q0 + r) * 64 + lc * 8);
        cp16(sb + OFF_K0 + SW_OFF(r, lc), Kg + (size_t)r * 64 + lc * 8);
        cp16(sb + OFF_V0 + SW_OFF(r, lc), Vg + (size_t)r * 1024 + lc * 8);
    }
    cp_commit();
    /* preload G1: both 128-row bands for kt=0 */
    {
        int w01 = q0 + 449, w02 = 449 - q0;
#pragma unroll
        for (int i = 0; i < 8; i++) {
            int r = lr + 16 * i;
            int pv = w01 + r;
            cp16(uB1 + SW_OFF(pv & 127, lc), PKg + (size_t)min(max(pv, 0), 1023) * 64 + lc * 8);
            int pv2 = w02 + r;
            cp16(uB2 + SW_OFF(pv2 & 127, lc), PQg + (size_t)min(max(pv2, 0), 1023) * 64 + lc * 8);
        }
    }
    cp_commit();

    float O[8][4];
#pragma unroll
    for (int i = 0; i < 8; i++)
#pragma unroll
        for (int j = 0; j < 4; j++) O[i][j] = 0.f;
    float lA = 0.f, lB = 0.f;
    uint32_t aQ[4][4];

    for (int kt = 0; kt < 16; kt++) {
        int k0 = kt << 6;
        int w01 = q0 - k0 + 449;
        int w02 = k0 - q0 + 449;
        uint32_t uK = sb + ((kt & 1) ? OFF_K1 : OFF_K0);
        uint32_t uV = sb + ((kt & 1) ? OFF_V1 : OFF_V0);

        __syncthreads(); /* S0 */

        if (kt < 15) {
            uint32_t nK = sb + ((kt & 1) ? OFF_K0 : OFF_K1);
            uint32_t nV = sb + ((kt & 1) ? OFF_V0 : OFF_V1);
            int nk0 = k0 + 64;
#pragma unroll
            for (int i = 0; i < 4; i++) {
                int r = lr + 16 * i;
                cp16(nK + SW_OFF(r, lc), Kg + (size_t)(nk0 + r) * 64 + lc * 8);
                cp16(nV + SW_OFF(r, lc), Vg + (size_t)r * 1024 + nk0 + lc * 8);
            }
            cp_commit();
            cp_wait<1>();
        } else {
            cp_wait<0>();
        }
        __syncthreads(); /* S1 */

        if (kt == 0) {
#pragma unroll
            for (int ks = 0; ks < 4; ks++)
                ldsm4(aQ[ks], uQ + SW_OFF(aw_row, ks * 2 + (lane >> 4)));
        }

        /* ---- c2p band mma ---- */
        {
            int npass = (kt == 0) ? 2 : 1;
            for (int pass = 0; pass < npass; pass++) {
                int npb = (kt == 0) ? pass * 4 : 0;
                float acc[8][4];
#pragma unroll
                for (int i = 0; i < 8; i++)
#pragma unroll
                    for (int j = 0; j < 4; j++) acc[i][j] = 0.f;
#pragma unroll
                for (int ks = 0; ks < 4; ks++) {
#pragma unroll
                    for (int np = 0; np < 4; np++) {
                        uint32_t bq[4];
                        int slot = (w01 + (npb + np) * 16 + fr_row) & 127;
                        ldsm4(bq, uB1 + SW_OFF(slot, ks * 2 + fr_khb));
                        mma16(acc[np * 2], aQ[ks], bq);
                        mma16(acc[np * 2 + 1], aQ[ks], bq + 2);
                    }
                }
#pragma unroll
                for (int f = 0; f < 8; f++) {
                    int col = npb * 16 + f * 8 + q2 * 2;
                    C2A[(k0 + 63 + qiA - col) & 127] = __float2half_rn(acc[f][0]);
                    C2A[(k0 + 62 + qiA - col) & 127] = __float2half_rn(acc[f][1]);
                    C2B[(k0 + 63 + qiB - col) & 127] = __float2half_rn(acc[f][2]);
                    C2B[(k0 + 62 + qiB - col) & 127] = __float2half_rn(acc[f][3]);
                }
            }
        }

        /* ---- p2c band mma: 5 ring groups; unconditional padded stores ---- */
        {
            float acc[10][4];
#pragma unroll
            for (int i = 0; i < 10; i++)
#pragma unroll
                for (int j = 0; j < 4; j++) acc[i][j] = 0.f;
#pragma unroll
            for (int ks = 0; ks < 4; ks++) {
                uint32_t a[4];
                ldsm4(a, uK + SW_OFF(aw_row, ks * 2 + (lane >> 4)));
#pragma unroll
                for (int j = 0; j < 5; j++) {
                    uint32_t bq[4];
                    int slot = (w02 + wq0 + j * 16 + fr_row) & 127;
                    ldsm4(bq, uB2 + SW_OFF(slot, ks * 2 + fr_khb));
                    mma16(acc[j * 2], a, bq);
                    mma16(acc[j * 2 + 1], a, bq + 2);
                }
            }
#pragma unroll
            for (int f = 0; f < 10; f++) {
                int col = wq0 + (f >> 1) * 16 + (f & 1) * 8 + q2 * 2;
                int rA = col - qiA + 16, rB = col - qiB + 16;
                P2p[rA * CW + qiA] = __float2half_rn(acc[f][0]);
                P2p[(rA + 1) * CW + qiA] = __float2half_rn(acc[f][1]);
                P2p[rB * CW + qiB] = __float2half_rn(acc[f][2]);
                P2p[(rB + 1) * CW + qiB] = __float2half_rn(acc[f][3]);
            }
        }

        /* ---- QK mma ---- */
        float sS[8][4];
#pragma unroll
        for (int i = 0; i < 8; i++)
#pragma unroll
            for (int j = 0; j < 4; j++) sS[i][j] = 0.f;
#pragma unroll
        for (int ks = 0; ks < 4; ks++) {
#pragma unroll
            for (int np = 0; np < 4; np++) {
                uint32_t bq[4];
                ldsm4(bq, uK + SW_OFF(np * 16 + fr_row, ks * 2 + fr_khb));
                mma16(sS[np * 2], aQ[ks], bq);
                mma16(sS[np * 2 + 1], aQ[ks], bq + 2);
            }
        }

        __syncthreads(); /* S2 */

        if (kt < 15) {
            int nw01 = w01 - 64;
            int nw02b = w02 + 128;
#pragma unroll
            for (int i = 0; i < 4; i++) {
                int r = lr + 16 * i;
                int pv = nw01 + r;
                cp16(uB1 + SW_OFF(pv & 127, lc), PKg + (size_t)min(max(pv, 0), 1023) * 64 + lc * 8);
                int pv2 = nw02b + r;
                cp16(uB2 + SW_OFF(pv2 & 127, lc), PQg + (size_t)min(max(pv2, 0), 1023) * 64 + lc * 8);
            }
            cp_commit();
        }

        /* ---- fixup (hadd2, hoisted bases) ---- */
#pragma unroll
        for (int nst = 0; nst < 8; nst++) {
            int kj = nst * 8 + q2 * 2;
            __half2 cA2 = __hadd2(*(__half2*)&C2A[(k0 + kj) & 127],
                                  *(__half2*)&P2A[kj]);
            __half2 cB2 = __hadd2(*(__half2*)&C2B[(k0 + kj) & 127],
                                  *(__half2*)&P2B[kj]);
            float2 fa = __half22float2(cA2);
            float2 fb = __half22float2(cB2);
            sS[nst][0] += fa.x;
            sS[nst][1] += fa.y;
            sS[nst][2] += fb.x;
            sS[nst][3] += fb.y;
        }

        /* ---- exp interleaved with PV mma; half2 l-accumulation ---- */
        __half2 lh2A = __float2half2_rn(0.f), lh2B = __float2half2_rn(0.f);
#pragma unroll
        for (int kc = 0; kc < 4; kc++) {
            uint32_t e[4];
            e[0] = ex2h2(sS[2 * kc][0], sS[2 * kc][1]);
            e[1] = ex2h2(sS[2 * kc][2], sS[2 * kc][3]);
            e[2] = ex2h2(sS[2 * kc + 1][0], sS[2 * kc + 1][1]);
            e[3] = ex2h2(sS[2 * kc + 1][2], sS[2 * kc + 1][3]);
            lh2A = __hadd2(lh2A, __hadd2(*(__half2*)&e[0], *(__half2*)&e[2]));
            lh2B = __hadd2(lh2B, __hadd2(*(__half2*)&e[1], *(__half2*)&e[3]));
#pragma unroll
            for (int np = 0; np < 4; np++) {
                uint32_t bq[4];
                ldsm4(bq, uV + SW_OFF(np * 16 + fr_row, kc * 2 + fr_khb));
                mma16(O[np * 2], e, bq);
                mma16(O[np * 2 + 1], e, bq + 2);
            }
        }
        {
            float2 fA = __half22float2(lh2A);
            float2 fB = __half22float2(lh2B);
            lA += fA.x + fA.y;
            lB += fB.x + fB.y;
        }
    }

    /* ---- deferred l reduction + epilogue ---- */
    lA += __shfl_xor_sync(0xffffffffu, lA, 1, 4);
    lA += __shfl_xor_sync(0xffffffffu, lA, 2, 4);
    lB += __shfl_xor_sync(0xffffffffu, lB, 1, 4);
    lB += __shfl_xor_sync(0xffffffffu, lB, 2, 4);
    float invA = 1.f / lA, invB = 1.f / lB;
    __half* ctxA = &g_CTX[((size_t)(b * 1024) + q0 + qiA) * 1024 + h * 64 + q2 * 2];
    __half* ctxB = &g_CTX[((size_t)(b * 1024) + q0 + qiB) * 1024 + h * 64 + q2 * 2];
#pragma unroll
    for (int np = 0; np < 8; np++) {
        *(__half2*)&ctxA[np * 8] = __floats2half2_rn(O[np][0] * invA, O[np][1] * invA);
        *(__half2*)&ctxB[np * 8] = __floats2half2_rn(O[np][2] * invB, O[np][3] * invB);
    }
}

/* ---------------- LayerNorm ---------------- */
__global__ void __launch_bounds__(256) k_ln(const float* __restrict__ gam,
                                            const float* __restrict__ bet,
                                            float* __restrict__ out) {
    int m = blockIdx.x;
    int tid = threadIdx.x;
    const float* y = g_Y + (size_t)m * Hh;
    float4 v = *(const float4*)(y + (tid << 2));
    float s = v.x + v.y + v.z + v.w;
    float s2 = v.x * v.x + v.y * v.y + v.z * v.z + v.w * v.w;
#pragma unroll
    for (int o = 16; o; o >>= 1) {
        s += __shfl_xor_sync(0xffffffffu, s, o);
        s2 += __shfl_xor_sync(0xffffffffu, s2, o);
    }
    __shared__ float sh[8], sh2[8];
    int w = tid >> 5, ln = tid & 31;
    if (ln == 0) { sh[w] = s; sh2[w] = s2; }
    __syncthreads();
    s = 0.f; s2 = 0.f;
#pragma unroll
    for (int i = 0; i < 8; i++) { s += sh[i]; s2 += sh2[i]; }
    float mean = s * (1.0f / Hh);
    float var = s2 * (1.0f / Hh) - mean * mean;
    float inv = rsqrtf(var + 1e-7f);
    float4 g4 = *(const float4*)(gam + (tid << 2));
    float4 b4 = *(const float4*)(bet + (tid << 2));
    float4 o4;
    o4.x = g4.x * (v.x - mean) * inv + b4.x;
    o4.y = g4.y * (v.y - mean) * inv + b4.y;
    o4.z = g4.z * (v.z - mean) * inv + b4.z;
    o4.w = g4.w * (v.w - mean) * inv + b4.w;
    *(float4*)(out + (size_t)m * Hh + (tid << 2)) = o4;
}

/* ---------------- launch ---------------- */
extern "C" void kernel_launch(void* const* d_in, const int* in_sizes, int n_in,
                              void* d_out, int out_size) {
    const float* hs   = (const float*)d_in[0];
    const float* re   = (const float*)d_in[2];
    const float* w_in = (const float*)d_in[3];
    const float* qb   = (const float*)d_in[4];
    const float* vb   = (const float*)d_in[5];
    const float* w_pk = (const float*)d_in[6];
    const float* w_pq = (const float*)d_in[7];
    const float* b_pq = (const float*)d_in[8];
    const float* w_o  = (const float*)d_in[9];
    const float* b_o  = (const float*)d_in[10];
    const float* lng  = (const float*)d_in[11];
    const float* lnb  = (const float*)d_in[12];
    float* out = (float*)d_out;

    static int attr_set = 0;
    if (!attr_set) {
        cudaFuncSetAttribute(k_attn2, cudaFuncAttributeMaxDynamicSharedMemorySize, ATTN_SMEM);
        cudaFuncSetAttribute(gemm_all, cudaFuncAttributeMaxDynamicSharedMemorySize, GEMM_SMEM);
        attr_set = 1;
    }

    k_round2<<<5120, 256>>>(hs, re);                                        /* 1 */
    k_transp2<<<dim3(32, 32, 6), 256>>>(w_in, w_pk, w_pq, w_o, 0);          /* 2 */
    gemm_all<<<896, 256, GEMM_SMEM>>>(0, qb, vb, b_pq, b_o, hs);            /* 3 */
    k_attn2<<<dim3(16, 64), 128, ATTN_SMEM>>>();                            /* 4: profiled */
    gemm_all<<<256, 256, GEMM_SMEM>>>(4, qb, vb, b_pq, b_o, hs);            /* 5 */
    k_ln<<<4096, 256>>>(lng, lnb, out);                                     /* 6 */
}